// round 1
// baseline (speedup 1.0000x reference)
#include <cuda_runtime.h>
#include <cuda_bf16.h>
#include <cstdint>

// ---------------------------------------------------------------------------
// Problem constants: B=1, L=512, C_S=384, H=12, D=32
// ---------------------------------------------------------------------------
#define LSEQ   512
#define CS     384
#define NH     12
#define HD     32
#define ZROWS  (LSEQ*LSEQ)          // 262144 rows of z
#define PLANE  (LSEQ*LSEQ)          // one [l][m] plane

// Scratch (device globals: no allocation inside kernel_launch)
__device__ float g_q[LSEQ*CS];            // q[l][h*32+d]
__device__ float g_kv[LSEQ*2*CS];         // kv[l][two*384 + h*32 + d]
__device__ float g_biasg[24ull*PLANE];    // [n][l*512+m]; n<12 bias head n, n>=12 gate-logit head n-12
__device__ float g_o[LSEQ*CS];            // o[l][h*32+d]

// ---------------------------------------------------------------------------
// f32x2 helpers (sm_103a packed fp32 FMA)
// ---------------------------------------------------------------------------
__device__ __forceinline__ void ffma2(unsigned long long &d, unsigned long long a, unsigned long long b) {
    asm("fma.rn.f32x2 %0, %1, %2, %0;" : "+l"(d) : "l"(a), "l"(b));
}
__device__ __forceinline__ unsigned long long pack2same(float w) {
    unsigned long long r;
    asm("mov.b64 %0, {%1, %1};" : "=l"(r) : "f"(w));
    return r;
}
__device__ __forceinline__ float2 unpack2(unsigned long long v) {
    float2 r;
    asm("mov.b64 {%0, %1}, %2;" : "=f"(r.x), "=f"(r.y) : "l"(v));
    return r;
}
__device__ __forceinline__ float f4c(const float4 &v, int i) {
    return (i == 0) ? v.x : (i == 1) ? v.y : (i == 2) ? v.z : v.w;
}

// ---------------------------------------------------------------------------
// Kernel: z projection (bias + gate fused).  C[262144][24] = z[262144][384] @ W[384][24]
// Block: 128 rows x 24 cols, 128 threads; thread tile = 8 rows (4 f32x2) x 3 cols.
// ---------------------------------------------------------------------------
__global__ void __launch_bounds__(128) zproj_kernel(
    const float* __restrict__ z,
    const float* __restrict__ Wb, const float* __restrict__ bb,
    const float* __restrict__ Wg, const float* __restrict__ bg,
    float* __restrict__ bias_g)
{
    __shared__ __align__(16) float ws[24][CS];   // [n][k]  (transposed weights)
    __shared__ __align__(16) float zs[16][132];  // [k][row], padded to 132 floats

    const int tid = threadIdx.x;

    // Load fused weights, transposed to [n][k]
    for (int i = tid; i < 24*CS; i += 128) {
        int n = i / CS, k = i % CS;
        ws[n][k] = (n < NH) ? Wb[k*NH + n] : Wg[k*NH + (n - NH)];
    }

    const int rg = tid >> 3;       // 0..15 : row group (8 rows)
    const int cg = tid & 7;        // 0..7  : col group (3 cols)
    const int n0 = cg * 3;
    const size_t rowbase = (size_t)blockIdx.x * 128;

    unsigned long long acc[3][4];
    #pragma unroll
    for (int j = 0; j < 3; j++)
        #pragma unroll
        for (int i = 0; i < 4; i++) acc[j][i] = 0ull;

    for (int kc = 0; kc < CS; kc += 16) {
        __syncthreads();  // previous compute done (first iter: after ws writes)
        // Load z tile [128 rows][16 k], coalesced, transposed into zs
        #pragma unroll
        for (int i = 0; i < 4; i++) {
            int f = i*128 + tid;            // 0..511
            int r = f >> 2, q4 = f & 3;
            float4 v = *(const float4*)(z + (rowbase + r)*(size_t)CS + kc + q4*4);
            zs[q4*4+0][r] = v.x;
            zs[q4*4+1][r] = v.y;
            zs[q4*4+2][r] = v.z;
            zs[q4*4+3][r] = v.w;
        }
        __syncthreads();

        #pragma unroll
        for (int k4 = 0; k4 < 4; k4++) {
            float4 w0 = *(const float4*)&ws[n0+0][kc + k4*4];
            float4 w1 = *(const float4*)&ws[n0+1][kc + k4*4];
            float4 w2 = *(const float4*)&ws[n0+2][kc + k4*4];
            #pragma unroll
            for (int kk = 0; kk < 4; kk++) {
                int k = k4*4 + kk;
                ulonglong2 A0 = *(const ulonglong2*)&zs[k][rg*8];
                ulonglong2 A1 = *(const ulonglong2*)&zs[k][rg*8 + 4];
                unsigned long long a[4] = {A0.x, A0.y, A1.x, A1.y};
                unsigned long long b0 = pack2same(f4c(w0, kk));
                unsigned long long b1 = pack2same(f4c(w1, kk));
                unsigned long long b2 = pack2same(f4c(w2, kk));
                #pragma unroll
                for (int i = 0; i < 4; i++) {
                    ffma2(acc[0][i], a[i], b0);
                    ffma2(acc[1][i], a[i], b1);
                    ffma2(acc[2][i], a[i], b2);
                }
            }
        }
    }

    #pragma unroll
    for (int j = 0; j < 3; j++) {
        int n = n0 + j;
        float bn = (n < NH) ? bb[n] : bg[n - NH];
        float* dst = bias_g + (size_t)n * PLANE + rowbase + rg*8;
        #pragma unroll
        for (int i = 0; i < 4; i++) {
            float2 p = unpack2(acc[j][i]);
            *(float2*)(dst + i*2) = make_float2(p.x + bn, p.y + bn);
        }
    }
}

// ---------------------------------------------------------------------------
// Generic tiled GEMM: C[M][N] = A[M][K] @ B[K][N] + bias[N]
// BM=BN=64, BK=16, 256 threads, thread tile 4x4. M,N,K divisible by tile dims.
// ---------------------------------------------------------------------------
__global__ void __launch_bounds__(256) gemm_bias_kernel(
    const float* __restrict__ A, const float* __restrict__ B,
    const float* __restrict__ bias, float* __restrict__ C,
    int M, int N, int K)
{
    __shared__ __align__(16) float As[16][68];
    __shared__ __align__(16) float Bs[16][64];

    const int tid = threadIdx.x;
    const int nt = N >> 6;
    const int bm = blockIdx.x / nt, bn = blockIdx.x % nt;
    const int rb = bm * 64, cb = bn * 64;
    const int tx = tid & 15, ty = tid >> 4;
    const int ar = tid >> 2, aq = tid & 3;
    const int bk = tid >> 4, bn4 = tid & 15;

    float acc[4][4] = {};

    for (int kc = 0; kc < K; kc += 16) {
        __syncthreads();
        {
            float4 v = *(const float4*)(A + (size_t)(rb + ar)*K + kc + aq*4);
            As[aq*4+0][ar] = v.x;
            As[aq*4+1][ar] = v.y;
            As[aq*4+2][ar] = v.z;
            As[aq*4+3][ar] = v.w;
            *(float4*)&Bs[bk][bn4*4] = *(const float4*)(B + (size_t)(kc + bk)*N + cb + bn4*4);
        }
        __syncthreads();
        #pragma unroll
        for (int kk = 0; kk < 16; kk++) {
            float4 a4 = *(const float4*)&As[kk][ty*4];
            float4 b4 = *(const float4*)&Bs[kk][tx*4];
            float aa[4] = {a4.x, a4.y, a4.z, a4.w};
            float bbv[4] = {b4.x, b4.y, b4.z, b4.w};
            #pragma unroll
            for (int i = 0; i < 4; i++)
                #pragma unroll
                for (int j = 0; j < 4; j++)
                    acc[i][j] += aa[i] * bbv[j];
        }
    }

    float4 bias4 = *(const float4*)(bias + cb + tx*4);
    #pragma unroll
    for (int i = 0; i < 4; i++) {
        float4 o = make_float4(acc[i][0] + bias4.x, acc[i][1] + bias4.y,
                               acc[i][2] + bias4.z, acc[i][3] + bias4.w);
        *(float4*)(C + (size_t)(rb + ty*4 + i)*N + cb + tx*4) = o;
    }
}

// ---------------------------------------------------------------------------
// Fused attention: per (h,l) block.  logits = q.k/sqrt(D) + bias, mask, softmax,
// * sigmoid(gate), then o = attn @ v.
// ---------------------------------------------------------------------------
__global__ void __launch_bounds__(256) attn_kernel(
    const float* __restrict__ qb, const float* __restrict__ kvb,
    const float* __restrict__ bias_g, const int* __restrict__ mask,
    float* __restrict__ ob)
{
    const int h = blockIdx.x >> 9;
    const int l = blockIdx.x & 511;
    const int tid = threadIdx.x;

    __shared__ float qsh[HD];
    __shared__ float psh[LSEQ];
    __shared__ float redm[8], reds[8];
    __shared__ float vred[8][33];

    if (tid < HD) qsh[tid] = qb[l*CS + h*HD + tid];
    __syncthreads();

    const int ml = mask[l];
    const float scale = 0.17677669529663687f;  // 1/sqrt(32)

    float lo[2], gate[2], p[2];
    float lmax = -3.0e38f;
    #pragma unroll
    for (int t = 0; t < 2; t++) {
        int m = tid + t*256;
        const float4* k4 = (const float4*)(kvb + (size_t)m*(2*CS) + h*HD);
        float dot = 0.f;
        #pragma unroll
        for (int i = 0; i < 8; i++) {
            float4 kv4 = k4[i];
            dot += qsh[i*4+0]*kv4.x + qsh[i*4+1]*kv4.y
                 + qsh[i*4+2]*kv4.z + qsh[i*4+3]*kv4.w;
        }
        float bias = bias_g[(size_t)h*PLANE + l*LSEQ + m];
        float gz   = bias_g[(size_t)(NH + h)*PLANE + l*LSEQ + m];
        gate[t] = 1.f / (1.f + __expf(-gz));
        float lg = dot*scale + bias;
        if (ml == 0 || mask[m] == 0) lg = -1.0e9f;
        lo[t] = lg;
        lmax = fmaxf(lmax, lg);
    }

    // block-wide max
    #pragma unroll
    for (int o = 16; o > 0; o >>= 1) lmax = fmaxf(lmax, __shfl_xor_sync(0xffffffffu, lmax, o));
    if ((tid & 31) == 0) redm[tid >> 5] = lmax;
    __syncthreads();
    float rowmax = redm[0];
    #pragma unroll
    for (int w = 1; w < 8; w++) rowmax = fmaxf(rowmax, redm[w]);

    float lsum = 0.f;
    #pragma unroll
    for (int t = 0; t < 2; t++) { p[t] = __expf(lo[t] - rowmax); lsum += p[t]; }
    #pragma unroll
    for (int o = 16; o > 0; o >>= 1) lsum += __shfl_xor_sync(0xffffffffu, lsum, o);
    if ((tid & 31) == 0) reds[tid >> 5] = lsum;
    __syncthreads();
    float rowsum = 0.f;
    #pragma unroll
    for (int w = 0; w < 8; w++) rowsum += reds[w];
    float inv = 1.f / rowsum;

    #pragma unroll
    for (int t = 0; t < 2; t++) psh[tid + t*256] = p[t] * inv * gate[t];
    __syncthreads();

    // o[d] = sum_m attn[m] * v[m][d]
    const int d = tid & 31, g = tid >> 5;
    float oacc = 0.f;
    const float* vbase = kvb + CS + h*HD + d;
    #pragma unroll 8
    for (int m = g; m < LSEQ; m += 8)
        oacc += psh[m] * vbase[(size_t)m*(2*CS)];
    vred[g][d] = oacc;
    __syncthreads();
    if (tid < 32) {
        float s = 0.f;
        #pragma unroll
        for (int gg = 0; gg < 8; gg++) s += vred[gg][tid];
        ob[l*CS + h*HD + tid] = s;
    }
}

// ---------------------------------------------------------------------------
// Launch
// ---------------------------------------------------------------------------
extern "C" void kernel_launch(void* const* d_in, const int* in_sizes, int n_in,
                              void* d_out, int out_size)
{
    (void)in_sizes; (void)n_in; (void)out_size;
    const float* s    = (const float*)d_in[0];
    const float* z    = (const float*)d_in[1];
    const int*   mask = (const int*)  d_in[2];
    const float* Wq   = (const float*)d_in[3];
    const float* bq   = (const float*)d_in[4];
    const float* Wkv  = (const float*)d_in[5];
    const float* bkv  = (const float*)d_in[6];
    const float* Wb   = (const float*)d_in[7];
    const float* bb   = (const float*)d_in[8];
    const float* Wg   = (const float*)d_in[9];
    const float* bg   = (const float*)d_in[10];
    const float* Wout = (const float*)d_in[11];
    const float* bout = (const float*)d_in[12];
    float* out = (float*)d_out;

    float *gq, *gkv, *gbg, *go;
    cudaGetSymbolAddress((void**)&gq,  g_q);
    cudaGetSymbolAddress((void**)&gkv, g_kv);
    cudaGetSymbolAddress((void**)&gbg, g_biasg);
    cudaGetSymbolAddress((void**)&go,  g_o);

    // q and kv projections
    gemm_bias_kernel<<<(LSEQ/64)*(CS/64),   256>>>(s, Wq,  bq,  gq,  LSEQ, CS,   CS);
    gemm_bias_kernel<<<(LSEQ/64)*(2*CS/64), 256>>>(s, Wkv, bkv, gkv, LSEQ, 2*CS, CS);

    // fused bias+gate projection of z (the heavy one)
    zproj_kernel<<<ZROWS/128, 128>>>(z, Wb, bb, Wg, bg, gbg);

    // fused attention
    attn_kernel<<<NH*LSEQ, 256>>>(gq, gkv, gbg, mask, go);

    // output projection
    gemm_bias_kernel<<<(LSEQ/64)*(CS/64), 256>>>(go, Wout, bout, out, LSEQ, CS, CS);
}

// round 2
// speedup vs baseline: 2.1326x; 2.1326x over previous
#include <cuda_runtime.h>
#include <cuda_bf16.h>
#include <cstdint>

// ---------------------------------------------------------------------------
// Problem constants: B=1, L=512, C_S=384, H=12, D=32
// ---------------------------------------------------------------------------
#define LSEQ   512
#define CS     384
#define NH     12
#define HD     32
#define ZROWS  (LSEQ*LSEQ)
#define PLANE  (LSEQ*LSEQ)
#define ZBM    256                   // rows per zproj block

// Scratch (device globals: no allocation inside kernel_launch)
__device__ float g_q[LSEQ*CS];
__device__ float g_kv[LSEQ*2*CS];
__device__ float g_biasg[24ull*PLANE];   // n<12: bias head n ; n>=12: gate logit head n-12
__device__ float g_o[LSEQ*CS];

// ---------------------------------------------------------------------------
// f32x2 helpers (sm_103a packed fp32 FMA)
// ---------------------------------------------------------------------------
__device__ __forceinline__ void ffma2(unsigned long long &d, unsigned long long a, unsigned long long b) {
    asm("fma.rn.f32x2 %0, %1, %2, %0;" : "+l"(d) : "l"(a), "l"(b));
}
__device__ __forceinline__ unsigned long long pack2same(float w) {
    unsigned long long r;
    asm("mov.b64 %0, {%1, %1};" : "=l"(r) : "f"(w));
    return r;
}
__device__ __forceinline__ float2 unpack2(unsigned long long v) {
    float2 r;
    asm("mov.b64 {%0, %1}, %2;" : "=f"(r.x), "=f"(r.y) : "l"(v));
    return r;
}
__device__ __forceinline__ float f4c(const float4 &v, int i) {
    return (i == 0) ? v.x : (i == 1) ? v.y : (i == 2) ? v.z : v.w;
}

// ---------------------------------------------------------------------------
// z projection (bias + gate fused).  C[262144][24] = z[262144][384] @ W[384][24]
// 256 threads, 256-row tiles, register-prefetch double buffering.
// Thread tile = 8 rows (4 f32x2) x 3 cols.
// ws padded to stride 388 (= 4 mod 32) so the 8 distinct n-rows per warp
// hit distinct banks (was 8-way conflicted at stride 384).
// ---------------------------------------------------------------------------
__global__ void __launch_bounds__(256) zproj_kernel(
    const float* __restrict__ z,
    const float* __restrict__ Wb, const float* __restrict__ bb,
    const float* __restrict__ Wg, const float* __restrict__ bg,
    float* __restrict__ bias_g)
{
    __shared__ __align__(16) float ws[24][CS+4];   // stride 388
    __shared__ __align__(16) float zs[16][ZBM+4];  // stride 260

    const int tid = threadIdx.x;

    for (int i = tid; i < 24*CS; i += 256) {
        int n = i / CS, k = i % CS;
        ws[n][k] = (n < NH) ? Wb[k*NH + n] : Wg[k*NH + (n - NH)];
    }

    const int rg = tid >> 3;      // 0..31 : row group (8 rows)
    const int cg = tid & 7;       // 0..7  : col group (3 cols)
    const int n0 = cg * 3;
    const size_t rowbase = (size_t)blockIdx.x * ZBM;

    unsigned long long acc[3][4];
    #pragma unroll
    for (int j = 0; j < 3; j++)
        #pragma unroll
        for (int i = 0; i < 4; i++) acc[j][i] = 0ull;

    // prefetch chunk 0 into registers
    float4 v[4];
    #pragma unroll
    for (int i = 0; i < 4; i++) {
        int f = i*256 + tid;            // 0..1023
        int r = f >> 2, q4 = f & 3;
        v[i] = *(const float4*)(z + (rowbase + r)*(size_t)CS + q4*4);
    }

    for (int kc = 0; kc < CS; kc += 16) {
        __syncthreads();   // previous compute done reading zs (iter 0: after ws writes)
        #pragma unroll
        for (int i = 0; i < 4; i++) {
            int f = i*256 + tid;
            int r = f >> 2, q4 = f & 3;
            zs[q4*4+0][r] = v[i].x;
            zs[q4*4+1][r] = v[i].y;
            zs[q4*4+2][r] = v[i].z;
            zs[q4*4+3][r] = v[i].w;
        }
        __syncthreads();

        // prefetch next chunk (overlaps with compute below)
        if (kc + 16 < CS) {
            #pragma unroll
            for (int i = 0; i < 4; i++) {
                int f = i*256 + tid;
                int r = f >> 2, q4 = f & 3;
                v[i] = *(const float4*)(z + (rowbase + r)*(size_t)CS + (kc+16) + q4*4);
            }
        }

        #pragma unroll
        for (int k4 = 0; k4 < 4; k4++) {
            float4 w0 = *(const float4*)&ws[n0+0][kc + k4*4];
            float4 w1 = *(const float4*)&ws[n0+1][kc + k4*4];
            float4 w2 = *(const float4*)&ws[n0+2][kc + k4*4];
            #pragma unroll
            for (int kk = 0; kk < 4; kk++) {
                int k = k4*4 + kk;
                ulonglong2 A0 = *(const ulonglong2*)&zs[k][rg*8];
                ulonglong2 A1 = *(const ulonglong2*)&zs[k][rg*8 + 4];
                unsigned long long a[4] = {A0.x, A0.y, A1.x, A1.y};
                unsigned long long b0 = pack2same(f4c(w0, kk));
                unsigned long long b1 = pack2same(f4c(w1, kk));
                unsigned long long b2 = pack2same(f4c(w2, kk));
                #pragma unroll
                for (int i = 0; i < 4; i++) {
                    ffma2(acc[0][i], a[i], b0);
                    ffma2(acc[1][i], a[i], b1);
                    ffma2(acc[2][i], a[i], b2);
                }
            }
        }
    }

    #pragma unroll
    for (int j = 0; j < 3; j++) {
        int n = n0 + j;
        float bn = (n < NH) ? bb[n] : bg[n - NH];
        float* dst = bias_g + (size_t)n * PLANE + rowbase + rg*8;
        #pragma unroll
        for (int i = 0; i < 4; i++) {
            float2 p = unpack2(acc[j][i]);
            *(float2*)(dst + i*2) = make_float2(p.x + bn, p.y + bn);
        }
    }
}

// ---------------------------------------------------------------------------
// Generic tiled GEMM: C[M][N] = A[M][K] @ B[K][N] + bias[N]
// ---------------------------------------------------------------------------
__global__ void __launch_bounds__(256) gemm_bias_kernel(
    const float* __restrict__ A, const float* __restrict__ B,
    const float* __restrict__ bias, float* __restrict__ C,
    int M, int N, int K)
{
    __shared__ __align__(16) float As[16][68];
    __shared__ __align__(16) float Bs[16][64];

    const int tid = threadIdx.x;
    const int nt = N >> 6;
    const int bm = blockIdx.x / nt, bn = blockIdx.x % nt;
    const int rb = bm * 64, cb = bn * 64;
    const int tx = tid & 15, ty = tid >> 4;
    const int ar = tid >> 2, aq = tid & 3;
    const int bk = tid >> 4, bn4 = tid & 15;

    float acc[4][4] = {};

    for (int kc = 0; kc < K; kc += 16) {
        __syncthreads();
        {
            float4 vv = *(const float4*)(A + (size_t)(rb + ar)*K + kc + aq*4);
            As[aq*4+0][ar] = vv.x;
            As[aq*4+1][ar] = vv.y;
            As[aq*4+2][ar] = vv.z;
            As[aq*4+3][ar] = vv.w;
            *(float4*)&Bs[bk][bn4*4] = *(const float4*)(B + (size_t)(kc + bk)*N + cb + bn4*4);
        }
        __syncthreads();
        #pragma unroll
        for (int kk = 0; kk < 16; kk++) {
            float4 a4 = *(const float4*)&As[kk][ty*4];
            float4 b4 = *(const float4*)&Bs[kk][tx*4];
            float aa[4] = {a4.x, a4.y, a4.z, a4.w};
            float bbv[4] = {b4.x, b4.y, b4.z, b4.w};
            #pragma unroll
            for (int i = 0; i < 4; i++)
                #pragma unroll
                for (int j = 0; j < 4; j++)
                    acc[i][j] += aa[i] * bbv[j];
        }
    }

    float4 bias4 = *(const float4*)(bias + cb + tx*4);
    #pragma unroll
    for (int i = 0; i < 4; i++) {
        float4 o = make_float4(acc[i][0] + bias4.x, acc[i][1] + bias4.y,
                               acc[i][2] + bias4.z, acc[i][3] + bias4.w);
        *(float4*)(C + (size_t)(rb + ty*4 + i)*N + cb + tx*4) = o;
    }
}

// ---------------------------------------------------------------------------
// Fused attention, 4 query rows per block.  Grid = 12 heads * 128 l-tiles.
// k staged coalesced through padded shared; v loads reused across 4 rows.
// ---------------------------------------------------------------------------
__global__ void __launch_bounds__(256) attn_kernel(
    const float* __restrict__ qb, const float* __restrict__ kvb,
    const float* __restrict__ bias_g, const int* __restrict__ mask,
    float* __restrict__ ob)
{
    const int h  = blockIdx.x >> 7;          // 0..11
    const int l0 = (blockIdx.x & 127) * 4;   // 4 query rows
    const int tid = threadIdx.x;

    __shared__ __align__(16) float qsh[4][HD+4];     // stride 36: conflict-free
    __shared__ __align__(16) float ksh[64][HD+4];    // stride 36
    __shared__ __align__(16) float psh[LSEQ][4];
    __shared__ int   msh[LSEQ];
    __shared__ int   mrow[4];
    __shared__ float redm[8][4], reds[8][4];
    __shared__ float vred[8][4][HD+1];

    if (tid < 128) qsh[tid>>5][tid&31] = qb[(size_t)(l0 + (tid>>5))*CS + h*HD + (tid&31)];
    if (tid < 4)   mrow[tid] = mask[l0 + tid];
    msh[tid]       = mask[tid];
    msh[tid + 256] = mask[tid + 256];
    __syncthreads();

    const float scale = 0.17677669529663687f;   // 1/sqrt(32)
    const int mlm = tid >> 2;       // 0..63 : m within tile
    const int lq  = tid & 3;        // 0..3  : query row
    const int rowok = mrow[lq];

    float lo[8], gt[8];
    float lmax = -3.0e38f;

    #pragma unroll
    for (int mt = 0; mt < 8; mt++) {
        __syncthreads();   // previous tile reads finished
        #pragma unroll
        for (int i = 0; i < 2; i++) {
            int f = i*256 + tid;           // float4 index 0..511
            int r = f >> 3, c4 = f & 7;
            *(float4*)&ksh[r][c4*4] =
                *(const float4*)(kvb + (size_t)(mt*64 + r)*(2*CS) + h*HD + c4*4);
        }
        __syncthreads();

        int m = mt*64 + mlm;
        float dot = 0.f;
        #pragma unroll
        for (int i = 0; i < 8; i++) {
            float4 kv4 = *(const float4*)&ksh[mlm][i*4];
            float4 q4  = *(const float4*)&qsh[lq][i*4];
            dot += q4.x*kv4.x + q4.y*kv4.y + q4.z*kv4.z + q4.w*kv4.w;
        }
        float bias = bias_g[(size_t)h*PLANE       + (size_t)(l0+lq)*LSEQ + m];
        float gz   = bias_g[(size_t)(NH+h)*PLANE  + (size_t)(l0+lq)*LSEQ + m];
        gt[mt] = 1.f / (1.f + __expf(-gz));
        float lg = dot*scale + bias;
        if (rowok == 0 || msh[m] == 0) lg = -1.0e9f;
        lo[mt] = lg;
        lmax = fmaxf(lmax, lg);
    }

    // reduce among lanes sharing lq (stride-4 groups), then across warps
    #pragma unroll
    for (int o = 4; o < 32; o <<= 1) lmax = fmaxf(lmax, __shfl_xor_sync(0xffffffffu, lmax, o));
    if ((tid & 31) < 4) redm[tid>>5][tid&3] = lmax;
    __syncthreads();
    float rm = redm[0][lq];
    #pragma unroll
    for (int w = 1; w < 8; w++) rm = fmaxf(rm, redm[w][lq]);

    float p[8];
    float lsum = 0.f;
    #pragma unroll
    for (int mt = 0; mt < 8; mt++) { p[mt] = __expf(lo[mt] - rm); lsum += p[mt]; }
    #pragma unroll
    for (int o = 4; o < 32; o <<= 1) lsum += __shfl_xor_sync(0xffffffffu, lsum, o);
    if ((tid & 31) < 4) reds[tid>>5][tid&3] = lsum;
    __syncthreads();
    float rs = 0.f;
    #pragma unroll
    for (int w = 0; w < 8; w++) rs += reds[w][lq];
    float inv = 1.f / rs;

    #pragma unroll
    for (int mt = 0; mt < 8; mt++)
        psh[mt*64 + mlm][lq] = p[mt] * inv * gt[mt];
    __syncthreads();

    // o[l][d] = sum_m psh[m][l] * v[m][d] ; each v load reused across 4 rows
    const int d = tid & 31, g = tid >> 5;
    float oa0 = 0.f, oa1 = 0.f, oa2 = 0.f, oa3 = 0.f;
    const float* vbase = kvb + CS + h*HD + d;
    #pragma unroll 4
    for (int m = g; m < LSEQ; m += 8) {
        float vv = vbase[(size_t)m*(2*CS)];
        float4 pp = *(const float4*)&psh[m][0];
        oa0 += pp.x*vv; oa1 += pp.y*vv; oa2 += pp.z*vv; oa3 += pp.w*vv;
    }
    vred[g][0][d] = oa0;
    vred[g][1][d] = oa1;
    vred[g][2][d] = oa2;
    vred[g][3][d] = oa3;
    __syncthreads();
    if (tid < 128) {
        int l = tid >> 5, dd = tid & 31;
        float s = 0.f;
        #pragma unroll
        for (int gg = 0; gg < 8; gg++) s += vred[gg][l][dd];
        ob[(size_t)(l0+l)*CS + h*HD + dd] = s;
    }
}

// ---------------------------------------------------------------------------
// Launch
// ---------------------------------------------------------------------------
extern "C" void kernel_launch(void* const* d_in, const int* in_sizes, int n_in,
                              void* d_out, int out_size)
{
    (void)in_sizes; (void)n_in; (void)out_size;
    const float* s    = (const float*)d_in[0];
    const float* z    = (const float*)d_in[1];
    const int*   mask = (const int*)  d_in[2];
    const float* Wq   = (const float*)d_in[3];
    const float* bq   = (const float*)d_in[4];
    const float* Wkv  = (const float*)d_in[5];
    const float* bkv  = (const float*)d_in[6];
    const float* Wb   = (const float*)d_in[7];
    const float* bb   = (const float*)d_in[8];
    const float* Wg   = (const float*)d_in[9];
    const float* bg   = (const float*)d_in[10];
    const float* Wout = (const float*)d_in[11];
    const float* bout = (const float*)d_in[12];
    float* out = (float*)d_out;

    float *gq, *gkv, *gbg, *go;
    cudaGetSymbolAddress((void**)&gq,  g_q);
    cudaGetSymbolAddress((void**)&gkv, g_kv);
    cudaGetSymbolAddress((void**)&gbg, g_biasg);
    cudaGetSymbolAddress((void**)&go,  g_o);

    gemm_bias_kernel<<<(LSEQ/64)*(CS/64),   256>>>(s, Wq,  bq,  gq,  LSEQ, CS,   CS);
    gemm_bias_kernel<<<(LSEQ/64)*(2*CS/64), 256>>>(s, Wkv, bkv, gkv, LSEQ, 2*CS, CS);

    zproj_kernel<<<ZROWS/ZBM, 256>>>(z, Wb, bb, Wg, bg, gbg);

    attn_kernel<<<NH*(LSEQ/4), 256>>>(gq, gkv, gbg, mask, go);

    gemm_bias_kernel<<<(LSEQ/64)*(CS/64), 256>>>(go, Wout, bout, out, LSEQ, CS, CS);
}